// round 14
// baseline (speedup 1.0000x reference)
#include <cuda_runtime.h>
#include <cuda_bf16.h>
#include <cuda_fp16.h>
#include <math.h>
#include <stdint.h>

#define MROWS 196608
#define SEQL 48
typedef __nv_bfloat16 bf16;

// ---------------- device scratch ----------------
__device__ __align__(128) bf16 g_wnt[512 * 512];
__device__ __align__(128) bf16 g_we1[1024 * 512];
__device__ __align__(128) bf16 g_we2[512 * 512];
__device__ __align__(128) bf16 g_wo[512 * 512];
__device__ __align__(128) bf16 g_wg[1024 * 512];
__device__ __align__(128) bf16 g_xbf[(size_t)MROWS * 512];
__device__ __align__(128) bf16 g_hbf[(size_t)MROWS * 512];   // h (bf16), later fp16 gate scratch
__device__ __align__(128) bf16 g_xt[(size_t)MROWS * 512];
__device__ __align__(128) bf16 g_wt[(size_t)MROWS * 512];
__device__ __align__(128) bf16 g_h1[(size_t)MROWS * 512];
__device__ __align__(128) bf16 g_msg[(size_t)MROWS * 512];
__device__ float g_adj[SEQL * SEQL];
__device__ int g_hasnb[SEQL];

__device__ __forceinline__ float geluf(float x) {
    return 0.5f * x * (1.0f + erff(x * 0.7071067811865476f));
}
__device__ __forceinline__ float sigf(float x) { return 1.f / (1.f + expf(-x)); }

__device__ __forceinline__ void cp16(unsigned dst, const void* src) {
    asm volatile("cp.async.cg.shared.global [%0], [%1], 16;\n" :: "r"(dst), "l"(src));
}

// ---------------- prep: x + all weights -> bf16 (single launch) ----------------
__global__ void k_prep(const float* __restrict__ x, const float* __restrict__ Wnt,
                       const float* __restrict__ We1, const float* __restrict__ We2,
                       const float* __restrict__ Wo, const float* __restrict__ Wg) {
    const long Q0 = (long)MROWS * 512 / 4;
    const long Q1 = 65536, Q2 = 131072, Q3 = 65536, Q4 = 65536, Q5 = 131072;
    const long QT = Q0 + Q1 + Q2 + Q3 + Q4 + Q5;
    for (long q = (long)blockIdx.x * blockDim.x + threadIdx.x; q < QT;
         q += (long)gridDim.x * blockDim.x) {
        const float* s; bf16* d; long o;
        if (q < Q0) { s = x; d = g_xbf; o = q; }
        else if (q < Q0 + Q1) { s = Wnt; d = g_wnt; o = q - Q0; }
        else if (q < Q0 + Q1 + Q2) { s = We1; d = g_we1; o = q - Q0 - Q1; }
        else if (q < Q0 + Q1 + Q2 + Q3) { s = We2; d = g_we2; o = q - Q0 - Q1 - Q2; }
        else if (q < Q0 + Q1 + Q2 + Q3 + Q4) { s = Wo; d = g_wo; o = q - Q0 - Q1 - Q2 - Q3; }
        else { s = Wg; d = g_wg; o = q - Q0 - Q1 - Q2 - Q3 - Q4; }
        float4 f = reinterpret_cast<const float4*>(s)[o];
        __nv_bfloat162 p0 = __floats2bfloat162_rn(f.x, f.y);
        __nv_bfloat162 p1 = __floats2bfloat162_rn(f.z, f.w);
        uint2 u;
        u.x = *reinterpret_cast<unsigned*>(&p0);
        u.y = *reinterpret_cast<unsigned*>(&p1);
        reinterpret_cast<uint2*>(d)[o] = u;
    }
}

__global__ void k_adj(const float* __restrict__ lw) {
    int i = threadIdx.x;
    if (i >= SEQL) return;
    float v[SEQL];
    float mx = -1e30f;
    #pragma unroll
    for (int j = 0; j < SEQL; j++) { v[j] = lw[i * SEQL + j]; mx = fmaxf(mx, v[j]); }
    float s = 0.f;
    #pragma unroll
    for (int j = 0; j < SEQL; j++) { v[j] = expf(v[j] - mx); s += v[j]; }
    float inv = 1.f / s;
    int any = 0;
    #pragma unroll
    for (int j = 0; j < SEQL; j++) {
        float a = v[j] * inv;
        int nb = (a > 0.01f);
        g_adj[i * SEQL + j] = nb ? a : 0.f;
        any |= nb;
    }
    g_hasnb[i] = any;
}

// ---------------- GEMM core (128x128, 256 thr, 3-stage, 2 CTA/SM) ----------
enum { EPI_HBF = 0, EPI_GELU = 1, EPI_MSG = 2 };

#define STAGES 3
#define ASTR 72
#define BSTR 136
#define A_ELEMS (128 * ASTR)
#define B_ELEMS (64 * BSTR)
#define SMEM_BYTES (STAGES * (A_ELEMS + B_ELEMS) * 2)

#define GEMM_PRELUDE                                                     \
    extern __shared__ bf16 smem[];                                       \
    const int tid = threadIdx.x;                                         \
    const int lane = tid & 31;                                           \
    const int wid = tid >> 5;                                            \
    const int wm = wid >> 1;                                             \
    const int wn = wid & 1;                                              \
    const int bn = blockIdx.x;                                           \
    const int bm = blockIdx.y;                                           \
    unsigned sbase = (unsigned)__cvta_generic_to_shared(smem);           \
    unsigned aB = sbase;                                                 \
    unsigned bB = sbase + STAGES * A_ELEMS * 2;

#define DEF_COMPUTE                                                                      \
    auto compute = [&](int st, float (&acc)[2][8][4]) {                                  \
        unsigned ab = aB + st * A_ELEMS * 2;                                             \
        unsigned bb = bB + st * B_ELEMS * 2;                                             \
        _Pragma("unroll")                                                                \
        for (int kk = 0; kk < 64; kk += 16) {                                            \
            unsigned a[2][4];                                                            \
            _Pragma("unroll")                                                            \
            for (int mi = 0; mi < 2; mi++) {                                             \
                int r = wm * 32 + mi * 16 + (lane & 15);                                 \
                int c = kk + ((lane >> 4) << 3);                                         \
                unsigned addr = ab + (unsigned)((r * ASTR + c) * 2);                     \
                asm volatile(                                                            \
                    "ldmatrix.sync.aligned.m8n8.x4.shared.b16 {%0,%1,%2,%3}, [%4];\n"    \
                    : "=r"(a[mi][0]), "=r"(a[mi][1]), "=r"(a[mi][2]), "=r"(a[mi][3])     \
                    : "r"(addr));                                                        \
            }                                                                            \
            unsigned b[4][4];                                                            \
            _Pragma("unroll")                                                            \
            for (int bi = 0; bi < 4; bi++) {                                             \
                int r = kk + (lane & 15);                                                \
                int c = wn * 64 + bi * 16 + ((lane >> 4) << 3);                          \
                unsigned addr = bb + (unsigned)((r * BSTR + c) * 2);                     \
                asm volatile(                                                            \
                    "ldmatrix.sync.aligned.m8n8.x4.trans.shared.b16 {%0,%1,%2,%3}, "     \
                    "[%4];\n"                                                            \
                    : "=r"(b[bi][0]), "=r"(b[bi][1]), "=r"(b[bi][2]), "=r"(b[bi][3])     \
                    : "r"(addr));                                                        \
            }                                                                            \
            _Pragma("unroll")                                                            \
            for (int mi = 0; mi < 2; mi++)                                               \
                _Pragma("unroll")                                                        \
                for (int ni = 0; ni < 8; ni++) {                                         \
                    unsigned b0 = b[ni >> 1][(ni & 1) * 2];                              \
                    unsigned b1 = b[ni >> 1][(ni & 1) * 2 + 1];                          \
                    asm volatile(                                                        \
                        "mma.sync.aligned.m16n8k16.row.col.f32.bf16.bf16.f32 "           \
                        "{%0,%1,%2,%3}, {%4,%5,%6,%7}, {%8,%9}, {%0,%1,%2,%3};\n"        \
                        : "+f"(acc[mi][ni][0]), "+f"(acc[mi][ni][1]),                    \
                          "+f"(acc[mi][ni][2]), "+f"(acc[mi][ni][3])                     \
                        : "r"(a[mi][0]), "r"(a[mi][1]), "r"(a[mi][2]), "r"(a[mi][3]),    \
                          "r"(b0), "r"(b1));                                             \
                }                                                                        \
        }                                                                                \
    };

#define DEF_LOADER                                                                       \
    auto load_stage = [&](int kt, int st, const bf16* A0, const bf16* A1,                \
                          const bf16* W, bool concat) {                                  \
        unsigned ab = aB + st * A_ELEMS * 2;                                             \
        unsigned bb = bB + st * B_ELEMS * 2;                                             \
        _Pragma("unroll")                                                                \
        for (int i = 0; i < 4; i++) {                                                    \
            int v = tid + (i << 8);                                                      \
            int row = v >> 3;                                                            \
            int kc = (v & 7) << 3;                                                       \
            long grow = (long)bm * 128 + row;                                            \
            int gk = kt * 64 + kc;                                                       \
            const bf16* src = (concat && gk >= 512) ? A1 + grow * 512 + (gk - 512)       \
                                                    : A0 + grow * 512 + gk;              \
            cp16(ab + (unsigned)((row * ASTR + kc) * 2), src);                           \
        }                                                                                \
        _Pragma("unroll")                                                                \
        for (int i = 0; i < 4; i++) {                                                    \
            int v = tid + (i << 8);                                                      \
            int row = v >> 4;                                                            \
            int nc = (v & 15) << 3;                                                      \
            cp16(bb + (unsigned)((row * BSTR + nc) * 2),                                 \
                 W + (long)(kt * 64 + row) * 512 + bn * 128 + nc);                       \
        }                                                                                \
        asm volatile("cp.async.commit_group;\n");                                       \
    };

#define RUN_PIPELINE(NK, A0, A1, W, CC, ACC)                                             \
    load_stage(0, 0, A0, A1, W, CC);                                                     \
    load_stage(1, 1, A0, A1, W, CC);                                                     \
    for (int kt = 0; kt < (NK); kt++) {                                                  \
        if (kt + 1 < (NK)) asm volatile("cp.async.wait_group 1;\n");                     \
        else asm volatile("cp.async.wait_group 0;\n");                                   \
        __syncthreads();                                                                 \
        if (kt + 2 < (NK)) load_stage(kt + 2, (kt + 2) % STAGES, A0, A1, W, CC);         \
        compute(kt % STAGES, ACC);                                                       \
    }

// ---------------- standalone GEMM ----------------
template <int KTOT, bool CONCAT, int EPI>
__global__ void __launch_bounds__(256, 2) gemm_k(
    const bf16* __restrict__ A0, const bf16* __restrict__ A1,
    const bf16* __restrict__ W, const float* __restrict__ bias,
    void* __restrict__ outp)
{
    GEMM_PRELUDE
    DEF_COMPUTE
    DEF_LOADER
    float acc[2][8][4] = {};
    const int nk = KTOT / 64;
    RUN_PIPELINE(nk, A0, A1, W, CONCAT, acc)

    long rbase = (long)bm * 128 + wm * 32;
    int cbase = bn * 128 + wn * 64;
    #pragma unroll
    for (int mi = 0; mi < 2; mi++) {
        #pragma unroll
        for (int ni = 0; ni < 8; ni++) {
            int c0 = cbase + ni * 8 + (lane & 3) * 2;
            float bv0 = bias[c0], bv1 = bias[c0 + 1];
            long r0 = rbase + mi * 16 + (lane >> 2);
            long r1 = r0 + 8;
            float v00 = acc[mi][ni][0] + bv0;
            float v01 = acc[mi][ni][1] + bv1;
            float v10 = acc[mi][ni][2] + bv0;
            float v11 = acc[mi][ni][3] + bv1;
            bf16* o = (bf16*)outp;
            if (EPI == EPI_GELU) {
                v00 = geluf(v00); v01 = geluf(v01);
                v10 = geluf(v10); v11 = geluf(v11);
            } else if (EPI == EPI_MSG) {
                int s0 = (int)(r0 % SEQL), s1 = (int)(r1 % SEQL);
                if (!g_hasnb[s0]) {
                    v00 = __bfloat162float(g_xt[r0 * 512 + c0]);
                    v01 = __bfloat162float(g_xt[r0 * 512 + c0 + 1]);
                }
                if (!g_hasnb[s1]) {
                    v10 = __bfloat162float(g_xt[r1 * 512 + c0]);
                    v11 = __bfloat162float(g_xt[r1 * 512 + c0 + 1]);
                }
            }
            __nv_bfloat162 p0 = __floats2bfloat162_rn(v00, v01);
            __nv_bfloat162 p1 = __floats2bfloat162_rn(v10, v11);
            *reinterpret_cast<__nv_bfloat162*>(o + r0 * 512 + c0) = p0;
            *reinterpret_cast<__nv_bfloat162*>(o + r1 * 512 + c0) = p1;
        }
    }
}

// ---- fused gate + Wo + blend; gate spilled to fp16 gmem scratch (L2-resident) ----
__global__ void __launch_bounds__(256, 2) gemm_fused(
    const bf16* __restrict__ xbf, const bf16* __restrict__ msg,
    const bf16* __restrict__ Wg, const float* __restrict__ bg,
    const bf16* __restrict__ Wo, const float* __restrict__ bo,
    const float* __restrict__ x, float* __restrict__ out,
    __half* __restrict__ gscratch)
{
    GEMM_PRELUDE
    DEF_COMPUTE
    DEF_LOADER

    long rbase = (long)bm * 128 + wm * 32;
    int cbase = bn * 128 + wn * 64;

    // phase 1: gate logits over [xbf | msg] @ Wg, K=1024
    {
        float accg[2][8][4] = {};
        RUN_PIPELINE(16, xbf, msg, Wg, true, accg)

        #pragma unroll
        for (int mi = 0; mi < 2; mi++)
            #pragma unroll
            for (int ni = 0; ni < 8; ni++) {
                int c0 = cbase + ni * 8 + (lane & 3) * 2;
                float b0 = bg[c0], b1 = bg[c0 + 1];
                long r0 = rbase + mi * 16 + (lane >> 2);
                long r1 = r0 + 8;
                __half2 h0 = __floats2half2_rn(sigf(accg[mi][ni][0] + b0),
                                               sigf(accg[mi][ni][1] + b1));
                __half2 h1 = __floats2half2_rn(sigf(accg[mi][ni][2] + b0),
                                               sigf(accg[mi][ni][3] + b1));
                *reinterpret_cast<__half2*>(gscratch + r0 * 512 + c0) = h0;
                *reinterpret_cast<__half2*>(gscratch + r1 * 512 + c0) = h1;
            }
    }

    __syncthreads();

    // phase 2: mo = msg @ Wo, K=512
    float acco[2][8][4] = {};
    RUN_PIPELINE(8, msg, msg, Wo, false, acco)

    #pragma unroll
    for (int mi = 0; mi < 2; mi++) {
        #pragma unroll
        for (int ni = 0; ni < 8; ni++) {
            int c0 = cbase + ni * 8 + (lane & 3) * 2;
            float b0 = bo[c0], b1 = bo[c0 + 1];
            long r0 = rbase + mi * 16 + (lane >> 2);
            long r1 = r0 + 8;
            __half2 h0 = *reinterpret_cast<const __half2*>(gscratch + r0 * 512 + c0);
            __half2 h1 = *reinterpret_cast<const __half2*>(gscratch + r1 * 512 + c0);
            float g00 = __half2float(h0.x), g01 = __half2float(h0.y);
            float g10 = __half2float(h1.x), g11 = __half2float(h1.y);
            float2 x0 = *reinterpret_cast<const float2*>(x + r0 * 512 + c0);
            float2 x1 = *reinterpret_cast<const float2*>(x + r1 * 512 + c0);
            float2 o0, o1;
            o0.x = g00 * (acco[mi][ni][0] + b0) + (1.f - g00) * x0.x;
            o0.y = g01 * (acco[mi][ni][1] + b1) + (1.f - g01) * x0.y;
            o1.x = g10 * (acco[mi][ni][2] + b0) + (1.f - g10) * x1.x;
            o1.y = g11 * (acco[mi][ni][3] + b1) + (1.f - g11) * x1.y;
            *reinterpret_cast<float2*>(out + r0 * 512 + c0) = o0;
            *reinterpret_cast<float2*>(out + r1 * 512 + c0) = o1;
        }
    }
}

// ------- k_lnmix: x_t = gelu(LN(h)); weighted = adj @ x_t  (fused, per batch) -------
#define MIX_ASTR 56
#define MIX_BSTR 520
#define MIX_SMEM ((48 * MIX_ASTR + 48 * MIX_BSTR) * 2)

__global__ void __launch_bounds__(256, 2) k_lnmix(const bf16* __restrict__ h,
                                                  const float* __restrict__ lg,
                                                  const float* __restrict__ lb) {
    extern __shared__ bf16 msm[];
    bf16* sadj = msm;                       // 48 x MIX_ASTR
    bf16* sxt = msm + 48 * MIX_ASTR;        // 48 x MIX_BSTR  (h, then x_t in place)
    const int b = blockIdx.x;
    const int tid = threadIdx.x;
    const int lane = tid & 31;
    const int wid = tid >> 5;

    // adj fp32 -> bf16 smem
    for (int i = tid; i < SEQL * SEQL; i += 256) {
        int r = i / SEQL, c = i - r * SEQL;
        sadj[r * MIX_ASTR + c] = __float2bfloat16(g_adj[i]);
    }
    // h batch tile: 48 rows x 512 cols
    const uint4* src = reinterpret_cast<const uint4*>(h + (size_t)b * SEQL * 512);
    for (int v = tid; v < SEQL * 64; v += 256) {
        int j = v >> 6, gq = v & 63;
        *reinterpret_cast<uint4*>(&sxt[j * MIX_BSTR + gq * 8]) = src[v];
    }
    __syncthreads();

    // LN + gelu in-smem: warp wid handles rows wid, wid+8, ..., wid+40
    bf16* xt_out = g_xt + (size_t)b * SEQL * 512;
    for (int rr = wid; rr < SEQL; rr += 8) {
        bf16* rowp = sxt + rr * MIX_BSTR;
        float v[16];
        float s = 0.f, s2 = 0.f;
        #pragma unroll
        for (int i = 0; i < 4; i++) {
            int c = (i * 32 + lane) * 4;
            uint2 u = *reinterpret_cast<const uint2*>(rowp + c);
            __nv_bfloat162 p0 = *reinterpret_cast<__nv_bfloat162*>(&u.x);
            __nv_bfloat162 p1 = *reinterpret_cast<__nv_bfloat162*>(&u.y);
            v[i * 4 + 0] = __bfloat162float(p0.x);
            v[i * 4 + 1] = __bfloat162float(p0.y);
            v[i * 4 + 2] = __bfloat162float(p1.x);
            v[i * 4 + 3] = __bfloat162float(p1.y);
            s += v[i * 4 + 0] + v[i * 4 + 1] + v[i * 4 + 2] + v[i * 4 + 3];
            s2 += v[i * 4 + 0] * v[i * 4 + 0] + v[i * 4 + 1] * v[i * 4 + 1] +
                  v[i * 4 + 2] * v[i * 4 + 2] + v[i * 4 + 3] * v[i * 4 + 3];
        }
        #pragma unroll
        for (int o = 16; o > 0; o >>= 1) {
            s += __shfl_xor_sync(0xffffffffu, s, o);
            s2 += __shfl_xor_sync(0xffffffffu, s2, o);
        }
        float mu = s * (1.f / 512.f);
        float var = s2 * (1.f / 512.f) - mu * mu;
        float rstd = rsqrtf(var + 1e-5f);
        #pragma unroll
        for (int i = 0; i < 4; i++) {
            int c = (i * 32 + lane) * 4;
            float4 gv = *reinterpret_cast<const float4*>(lg + c);
            float4 bv = *reinterpret_cast<const float4*>(lb + c);
            float y0 = geluf((v[i * 4 + 0] - mu) * rstd * gv.x + bv.x);
            float y1 = geluf((v[i * 4 + 1] - mu) * rstd * gv.y + bv.y);
            float y2 = geluf((v[i * 4 + 2] - mu) * rstd * gv.z + bv.z);
            float y3 = geluf((v[i * 4 + 3] - mu) * rstd * gv.w + bv.w);
            __nv_bfloat162 p0 = __floats2bfloat162_rn(y0, y1);
            __nv_bfloat162 p1 = __floats2bfloat162_rn(y2, y3);
            uint2 u;
            u.x = *reinterpret_cast<unsigned*>(&p0);
            u.y = *reinterpret_cast<unsigned*>(&p1);
            *reinterpret_cast<uint2*>(rowp + c) = u;
            *reinterpret_cast<uint2*>(xt_out + (long)rr * 512 + c) = u;
        }
    }
    __syncthreads();

    // MMA: weighted = sadj @ sxt (x_t now in smem)
    unsigned aBase = (unsigned)__cvta_generic_to_shared(sadj);
    unsigned bBase = (unsigned)__cvta_generic_to_shared(sxt);
    float acc[3][8][4] = {};
    const int nbase = wid * 64;

    #pragma unroll
    for (int kt = 0; kt < 3; kt++) {
        unsigned a[3][4];
        #pragma unroll
        for (int mt = 0; mt < 3; mt++) {
            int r = mt * 16 + (lane & 15);
            int c = kt * 16 + ((lane >> 4) << 3);
            unsigned addr = aBase + (unsigned)((r * MIX_ASTR + c) * 2);
            asm volatile("ldmatrix.sync.aligned.m8n8.x4.shared.b16 {%0,%1,%2,%3}, [%4];\n"
                         : "=r"(a[mt][0]), "=r"(a[mt][1]), "=r"(a[mt][2]), "=r"(a[mt][3])
                         : "r"(addr));
        }
        #pragma unroll
        for (int nt = 0; nt < 4; nt++) {
            unsigned bf[4];
            int r = kt * 16 + (lane & 15);
            int c = nbase + nt * 16 + ((lane >> 4) << 3);
            unsigned addr = bBase + (unsigned)((r * MIX_BSTR + c) * 2);
            asm volatile("ldmatrix.sync.aligned.m8n8.x4.trans.shared.b16 {%0,%1,%2,%3}, [%4];\n"
                         : "=r"(bf[0]), "=r"(bf[1]), "=r"(bf[2]), "=r"(bf[3])
                         : "r"(addr));
            #pragma unroll
            for (int mt = 0; mt < 3; mt++)
                #pragma unroll
                for (int nj = 0; nj < 2; nj++) {
                    int ni = nt * 2 + nj;
                    asm volatile(
                        "mma.sync.aligned.m16n8k16.row.col.f32.bf16.bf16.f32 "
                        "{%0,%1,%2,%3}, {%4,%5,%6,%7}, {%8,%9}, {%0,%1,%2,%3};\n"
                        : "+f"(acc[mt][ni][0]), "+f"(acc[mt][ni][1]),
                          "+f"(acc[mt][ni][2]), "+f"(acc[mt][ni][3])
                        : "r"(a[mt][0]), "r"(a[mt][1]), "r"(a[mt][2]), "r"(a[mt][3]),
                          "r"(bf[nj * 2]), "r"(bf[nj * 2 + 1]));
                }
        }
    }

    bf16* o = g_wt + (size_t)b * SEQL * 512;
    #pragma unroll
    for (int mt = 0; mt < 3; mt++) {
        #pragma unroll
        for (int ni = 0; ni < 8; ni++) {
            int c0 = nbase + ni * 8 + (lane & 3) * 2;
            int r0 = mt * 16 + (lane >> 2);
            int r1 = r0 + 8;
            __nv_bfloat162 p0 = __floats2bfloat162_rn(acc[mt][ni][0], acc[mt][ni][1]);
            __nv_bfloat162 p1 = __floats2bfloat162_rn(acc[mt][ni][2], acc[mt][ni][3]);
            *reinterpret_cast<__nv_bfloat162*>(o + (long)r0 * 512 + c0) = p0;
            *reinterpret_cast<__nv_bfloat162*>(o + (long)r1 * 512 + c0) = p1;
        }
    }
}

// ---------------- launch ----------------
extern "C" void kernel_launch(void* const* d_in, const int* in_sizes, int n_in,
                              void* d_out, int out_size) {
    const float* x = (const float*)d_in[0];
    const float* lw = (const float*)d_in[1];
    const float* Wnt = (const float*)d_in[2];
    const float* bnt = (const float*)d_in[3];
    const float* lng = (const float*)d_in[4];
    const float* lnb = (const float*)d_in[5];
    const float* We1 = (const float*)d_in[6];
    const float* be1 = (const float*)d_in[7];
    const float* We2 = (const float*)d_in[8];
    const float* be2 = (const float*)d_in[9];
    const float* Wo = (const float*)d_in[10];
    const float* bo = (const float*)d_in[11];
    const float* Wg = (const float*)d_in[12];
    const float* bg = (const float*)d_in[13];
    float* out = (float*)d_out;

    void *p_wnt, *p_we1, *p_we2, *p_wo, *p_wg, *p_xbf, *p_hbf, *p_xt, *p_wt, *p_h1, *p_msg;
    cudaGetSymbolAddress(&p_wnt, g_wnt);
    cudaGetSymbolAddress(&p_we1, g_we1);
    cudaGetSymbolAddress(&p_we2, g_we2);
    cudaGetSymbolAddress(&p_wo, g_wo);
    cudaGetSymbolAddress(&p_wg, g_wg);
    cudaGetSymbolAddress(&p_xbf, g_xbf);
    cudaGetSymbolAddress(&p_hbf, g_hbf);
    cudaGetSymbolAddress(&p_xt, g_xt);
    cudaGetSymbolAddress(&p_wt, g_wt);
    cudaGetSymbolAddress(&p_h1, g_h1);
    cudaGetSymbolAddress(&p_msg, g_msg);

    static bool attr_done = false;
    if (!attr_done) {
        cudaFuncSetAttribute(gemm_k<512, false, EPI_HBF>,
                             cudaFuncAttributeMaxDynamicSharedMemorySize, SMEM_BYTES);
        cudaFuncSetAttribute(gemm_k<1024, true, EPI_GELU>,
                             cudaFuncAttributeMaxDynamicSharedMemorySize, SMEM_BYTES);
        cudaFuncSetAttribute(gemm_k<512, false, EPI_MSG>,
                             cudaFuncAttributeMaxDynamicSharedMemorySize, SMEM_BYTES);
        cudaFuncSetAttribute(gemm_fused,
                             cudaFuncAttributeMaxDynamicSharedMemorySize, SMEM_BYTES);
        cudaFuncSetAttribute(k_lnmix,
                             cudaFuncAttributeMaxDynamicSharedMemorySize, MIX_SMEM);
        attr_done = true;
    }

    dim3 gg(4, MROWS / 128);  // 128x128 tiles, bn fast -> A-tile L2 reuse

    // 1: convert x + weights to bf16 (single launch)
    k_prep<<<2304, 256>>>(x, Wnt, We1, We2, Wo, Wg);
    // 2: adjacency
    k_adj<<<1, 64>>>(lw);
    // 3: h = x@Wnt + bnt (bf16 out)
    gemm_k<512, false, EPI_HBF><<<gg, 256, SMEM_BYTES>>>(
        (const bf16*)p_xbf, nullptr, (const bf16*)p_wnt, bnt, p_hbf);
    // 4 <- ncu capture: fused x_t = gelu(LN(h)); weighted = adj @ x_t
    k_lnmix<<<4096, 256, MIX_SMEM>>>((const bf16*)p_hbf, lng, lnb);
    // 5: h1 = gelu([x_t|wt]@We1 + be1)
    gemm_k<1024, true, EPI_GELU><<<gg, 256, SMEM_BYTES>>>(
        (const bf16*)p_xt, (const bf16*)p_wt, (const bf16*)p_we1, be1, p_h1);
    // 6: messages = blend(h1@We2 + be2, x_t)
    gemm_k<512, false, EPI_MSG><<<gg, 256, SMEM_BYTES>>>(
        (const bf16*)p_h1, nullptr, (const bf16*)p_we2, be2, p_msg);
    // 7: fused gate + Wo + blend -> out (h buffer reused as fp16 gate scratch)
    gemm_fused<<<gg, 256, SMEM_BYTES>>>(
        (const bf16*)p_xbf, (const bf16*)p_msg, (const bf16*)p_wg, bg,
        (const bf16*)p_wo, bo, x, out, (__half*)p_hbf);
}

// round 15
// speedup vs baseline: 1.0145x; 1.0145x over previous
#include <cuda_runtime.h>
#include <cuda_bf16.h>
#include <cuda_fp16.h>
#include <math.h>
#include <stdint.h>

#define MROWS 196608
#define SEQL 48
typedef __nv_bfloat16 bf16;

// ---------------- device scratch ----------------
__device__ __align__(128) bf16 g_wnt[512 * 512];
__device__ __align__(128) bf16 g_we1[1024 * 512];
__device__ __align__(128) bf16 g_we2[512 * 512];
__device__ __align__(128) bf16 g_wo[512 * 512];
__device__ __align__(128) bf16 g_wg[1024 * 512];
__device__ __align__(128) bf16 g_xbf[(size_t)MROWS * 512];
__device__ __align__(128) bf16 g_hbf[(size_t)MROWS * 512];   // h (bf16), later fp16 gate scratch
__device__ __align__(128) bf16 g_xt[(size_t)MROWS * 512];
__device__ __align__(128) bf16 g_wt[(size_t)MROWS * 512];
__device__ __align__(128) bf16 g_h1[(size_t)MROWS * 512];
__device__ __align__(128) bf16 g_msg[(size_t)MROWS * 512];
__device__ float g_adj[SEQL * SEQL];
__device__ int g_hasnb[SEQL];

__device__ __forceinline__ float geluf(float x) {
    return 0.5f * x * (1.0f + erff(x * 0.7071067811865476f));
}
__device__ __forceinline__ float sigf(float x) { return 1.f / (1.f + expf(-x)); }

__device__ __forceinline__ void cp16(unsigned dst, const void* src) {
    asm volatile("cp.async.cg.shared.global [%0], [%1], 16;\n" :: "r"(dst), "l"(src));
}

// ---------------- prep: x + all weights -> bf16 (single launch) ----------------
__global__ void k_prep(const float* __restrict__ x, const float* __restrict__ Wnt,
                       const float* __restrict__ We1, const float* __restrict__ We2,
                       const float* __restrict__ Wo, const float* __restrict__ Wg) {
    const long Q0 = (long)MROWS * 512 / 4;
    const long Q1 = 65536, Q2 = 131072, Q3 = 65536, Q4 = 65536, Q5 = 131072;
    const long QT = Q0 + Q1 + Q2 + Q3 + Q4 + Q5;
    for (long q = (long)blockIdx.x * blockDim.x + threadIdx.x; q < QT;
         q += (long)gridDim.x * blockDim.x) {
        const float* s; bf16* d; long o;
        if (q < Q0) { s = x; d = g_xbf; o = q; }
        else if (q < Q0 + Q1) { s = Wnt; d = g_wnt; o = q - Q0; }
        else if (q < Q0 + Q1 + Q2) { s = We1; d = g_we1; o = q - Q0 - Q1; }
        else if (q < Q0 + Q1 + Q2 + Q3) { s = We2; d = g_we2; o = q - Q0 - Q1 - Q2; }
        else if (q < Q0 + Q1 + Q2 + Q3 + Q4) { s = Wo; d = g_wo; o = q - Q0 - Q1 - Q2 - Q3; }
        else { s = Wg; d = g_wg; o = q - Q0 - Q1 - Q2 - Q3 - Q4; }
        float4 f = reinterpret_cast<const float4*>(s)[o];
        __nv_bfloat162 p0 = __floats2bfloat162_rn(f.x, f.y);
        __nv_bfloat162 p1 = __floats2bfloat162_rn(f.z, f.w);
        uint2 u;
        u.x = *reinterpret_cast<unsigned*>(&p0);
        u.y = *reinterpret_cast<unsigned*>(&p1);
        reinterpret_cast<uint2*>(d)[o] = u;
    }
}

__global__ void k_adj(const float* __restrict__ lw) {
    int i = threadIdx.x;
    if (i >= SEQL) return;
    float v[SEQL];
    float mx = -1e30f;
    #pragma unroll
    for (int j = 0; j < SEQL; j++) { v[j] = lw[i * SEQL + j]; mx = fmaxf(mx, v[j]); }
    float s = 0.f;
    #pragma unroll
    for (int j = 0; j < SEQL; j++) { v[j] = expf(v[j] - mx); s += v[j]; }
    float inv = 1.f / s;
    int any = 0;
    #pragma unroll
    for (int j = 0; j < SEQL; j++) {
        float a = v[j] * inv;
        int nb = (a > 0.01f);
        g_adj[i * SEQL + j] = nb ? a : 0.f;
        any |= nb;
    }
    g_hasnb[i] = any;
}

// ---------------- GEMM core (128x128, 256 thr, 3-stage, 2 CTA/SM) ----------
enum { EPI_HBF = 0, EPI_GELU = 1, EPI_MSG = 2 };

#define STAGES 3
#define ASTR 72
#define BSTR 136
#define A_ELEMS (128 * ASTR)
#define B_ELEMS (64 * BSTR)
#define SMEM_BYTES (STAGES * (A_ELEMS + B_ELEMS) * 2)

#define GEMM_PRELUDE                                                     \
    extern __shared__ bf16 smem[];                                       \
    const int tid = threadIdx.x;                                         \
    const int lane = tid & 31;                                           \
    const int wid = tid >> 5;                                            \
    const int wm = wid >> 1;                                             \
    const int wn = wid & 1;                                              \
    const int bn = blockIdx.x;                                           \
    const int bm = blockIdx.y;                                           \
    unsigned sbase = (unsigned)__cvta_generic_to_shared(smem);           \
    unsigned aB = sbase;                                                 \
    unsigned bB = sbase + STAGES * A_ELEMS * 2;

#define DEF_COMPUTE                                                                      \
    auto compute = [&](int st, float (&acc)[2][8][4]) {                                  \
        unsigned ab = aB + st * A_ELEMS * 2;                                             \
        unsigned bb = bB + st * B_ELEMS * 2;                                             \
        _Pragma("unroll")                                                                \
        for (int kk = 0; kk < 64; kk += 16) {                                            \
            unsigned a[2][4];                                                            \
            _Pragma("unroll")                                                            \
            for (int mi = 0; mi < 2; mi++) {                                             \
                int r = wm * 32 + mi * 16 + (lane & 15);                                 \
                int c = kk + ((lane >> 4) << 3);                                         \
                unsigned addr = ab + (unsigned)((r * ASTR + c) * 2);                     \
                asm volatile(                                                            \
                    "ldmatrix.sync.aligned.m8n8.x4.shared.b16 {%0,%1,%2,%3}, [%4];\n"    \
                    : "=r"(a[mi][0]), "=r"(a[mi][1]), "=r"(a[mi][2]), "=r"(a[mi][3])     \
                    : "r"(addr));                                                        \
            }                                                                            \
            unsigned b[4][4];                                                            \
            _Pragma("unroll")                                                            \
            for (int bi = 0; bi < 4; bi++) {                                             \
                int r = kk + (lane & 15);                                                \
                int c = wn * 64 + bi * 16 + ((lane >> 4) << 3);                          \
                unsigned addr = bb + (unsigned)((r * BSTR + c) * 2);                     \
                asm volatile(                                                            \
                    "ldmatrix.sync.aligned.m8n8.x4.trans.shared.b16 {%0,%1,%2,%3}, "     \
                    "[%4];\n"                                                            \
                    : "=r"(b[bi][0]), "=r"(b[bi][1]), "=r"(b[bi][2]), "=r"(b[bi][3])     \
                    : "r"(addr));                                                        \
            }                                                                            \
            _Pragma("unroll")                                                            \
            for (int mi = 0; mi < 2; mi++)                                               \
                _Pragma("unroll")                                                        \
                for (int ni = 0; ni < 8; ni++) {                                         \
                    unsigned b0 = b[ni >> 1][(ni & 1) * 2];                              \
                    unsigned b1 = b[ni >> 1][(ni & 1) * 2 + 1];                          \
                    asm volatile(                                                        \
                        "mma.sync.aligned.m16n8k16.row.col.f32.bf16.bf16.f32 "           \
                        "{%0,%1,%2,%3}, {%4,%5,%6,%7}, {%8,%9}, {%0,%1,%2,%3};\n"        \
                        : "+f"(acc[mi][ni][0]), "+f"(acc[mi][ni][1]),                    \
                          "+f"(acc[mi][ni][2]), "+f"(acc[mi][ni][3])                     \
                        : "r"(a[mi][0]), "r"(a[mi][1]), "r"(a[mi][2]), "r"(a[mi][3]),    \
                          "r"(b0), "r"(b1));                                             \
                }                                                                        \
        }                                                                                \
    };

#define DEF_LOADER                                                                       \
    auto load_stage = [&](int kt, int st, const bf16* A0, const bf16* A1,                \
                          const bf16* W, bool concat) {                                  \
        unsigned ab = aB + st * A_ELEMS * 2;                                             \
        unsigned bb = bB + st * B_ELEMS * 2;                                             \
        _Pragma("unroll")                                                                \
        for (int i = 0; i < 4; i++) {                                                    \
            int v = tid + (i << 8);                                                      \
            int row = v >> 3;                                                            \
            int kc = (v & 7) << 3;                                                       \
            long grow = (long)bm * 128 + row;                                            \
            int gk = kt * 64 + kc;                                                       \
            const bf16* src = (concat && gk >= 512) ? A1 + grow * 512 + (gk - 512)       \
                                                    : A0 + grow * 512 + gk;              \
            cp16(ab + (unsigned)((row * ASTR + kc) * 2), src);                           \
        }                                                                                \
        _Pragma("unroll")                                                                \
        for (int i = 0; i < 4; i++) {                                                    \
            int v = tid + (i << 8);                                                      \
            int row = v >> 4;                                                            \
            int nc = (v & 15) << 3;                                                      \
            cp16(bb + (unsigned)((row * BSTR + nc) * 2),                                 \
                 W + (long)(kt * 64 + row) * 512 + bn * 128 + nc);                       \
        }                                                                                \
        asm volatile("cp.async.commit_group;\n");                                       \
    };

#define RUN_PIPELINE(NK, A0, A1, W, CC, ACC)                                             \
    load_stage(0, 0, A0, A1, W, CC);                                                     \
    load_stage(1, 1, A0, A1, W, CC);                                                     \
    for (int kt = 0; kt < (NK); kt++) {                                                  \
        if (kt + 1 < (NK)) asm volatile("cp.async.wait_group 1;\n");                     \
        else asm volatile("cp.async.wait_group 0;\n");                                   \
        __syncthreads();                                                                 \
        if (kt + 2 < (NK)) load_stage(kt + 2, (kt + 2) % STAGES, A0, A1, W, CC);         \
        compute(kt % STAGES, ACC);                                                       \
    }

// ---------------- standalone GEMM ----------------
template <int KTOT, bool CONCAT, int EPI>
__global__ void __launch_bounds__(256, 2) gemm_k(
    const bf16* __restrict__ A0, const bf16* __restrict__ A1,
    const bf16* __restrict__ W, const float* __restrict__ bias,
    void* __restrict__ outp)
{
    GEMM_PRELUDE
    DEF_COMPUTE
    DEF_LOADER
    float acc[2][8][4] = {};
    const int nk = KTOT / 64;
    RUN_PIPELINE(nk, A0, A1, W, CONCAT, acc)

    long rbase = (long)bm * 128 + wm * 32;
    int cbase = bn * 128 + wn * 64;
    #pragma unroll
    for (int mi = 0; mi < 2; mi++) {
        #pragma unroll
        for (int ni = 0; ni < 8; ni++) {
            int c0 = cbase + ni * 8 + (lane & 3) * 2;
            float bv0 = bias[c0], bv1 = bias[c0 + 1];
            long r0 = rbase + mi * 16 + (lane >> 2);
            long r1 = r0 + 8;
            float v00 = acc[mi][ni][0] + bv0;
            float v01 = acc[mi][ni][1] + bv1;
            float v10 = acc[mi][ni][2] + bv0;
            float v11 = acc[mi][ni][3] + bv1;
            bf16* o = (bf16*)outp;
            if (EPI == EPI_GELU) {
                v00 = geluf(v00); v01 = geluf(v01);
                v10 = geluf(v10); v11 = geluf(v11);
            } else if (EPI == EPI_MSG) {
                int s0 = (int)(r0 % SEQL), s1 = (int)(r1 % SEQL);
                if (!g_hasnb[s0]) {
                    v00 = __bfloat162float(g_xt[r0 * 512 + c0]);
                    v01 = __bfloat162float(g_xt[r0 * 512 + c0 + 1]);
                }
                if (!g_hasnb[s1]) {
                    v10 = __bfloat162float(g_xt[r1 * 512 + c0]);
                    v11 = __bfloat162float(g_xt[r1 * 512 + c0 + 1]);
                }
            }
            __nv_bfloat162 p0 = __floats2bfloat162_rn(v00, v01);
            __nv_bfloat162 p1 = __floats2bfloat162_rn(v10, v11);
            *reinterpret_cast<__nv_bfloat162*>(o + r0 * 512 + c0) = p0;
            *reinterpret_cast<__nv_bfloat162*>(o + r1 * 512 + c0) = p1;
        }
    }
}

// ---- fused gate + Wo + blend; gate spilled to fp16 gmem scratch (L2-resident) ----
__global__ void __launch_bounds__(256, 2) gemm_fused(
    const bf16* __restrict__ xbf, const bf16* __restrict__ msg,
    const bf16* __restrict__ Wg, const float* __restrict__ bg,
    const bf16* __restrict__ Wo, const float* __restrict__ bo,
    const float* __restrict__ x, float* __restrict__ out,
    __half* __restrict__ gscratch)
{
    GEMM_PRELUDE
    DEF_COMPUTE
    DEF_LOADER

    long rbase = (long)bm * 128 + wm * 32;
    int cbase = bn * 128 + wn * 64;

    // phase 1: gate logits over [xbf | msg] @ Wg, K=1024
    {
        float accg[2][8][4] = {};
        RUN_PIPELINE(16, xbf, msg, Wg, true, accg)

        #pragma unroll
        for (int mi = 0; mi < 2; mi++)
            #pragma unroll
            for (int ni = 0; ni < 8; ni++) {
                int c0 = cbase + ni * 8 + (lane & 3) * 2;
                float b0 = bg[c0], b1 = bg[c0 + 1];
                long r0 = rbase + mi * 16 + (lane >> 2);
                long r1 = r0 + 8;
                __half2 h0 = __floats2half2_rn(sigf(accg[mi][ni][0] + b0),
                                               sigf(accg[mi][ni][1] + b1));
                __half2 h1 = __floats2half2_rn(sigf(accg[mi][ni][2] + b0),
                                               sigf(accg[mi][ni][3] + b1));
                *reinterpret_cast<__half2*>(gscratch + r0 * 512 + c0) = h0;
                *reinterpret_cast<__half2*>(gscratch + r1 * 512 + c0) = h1;
            }
    }

    __syncthreads();

    // phase 2: mo = msg @ Wo, K=512
    float acco[2][8][4] = {};
    RUN_PIPELINE(8, msg, msg, Wo, false, acco)

    #pragma unroll
    for (int mi = 0; mi < 2; mi++) {
        #pragma unroll
        for (int ni = 0; ni < 8; ni++) {
            int c0 = cbase + ni * 8 + (lane & 3) * 2;
            float b0 = bo[c0], b1 = bo[c0 + 1];
            long r0 = rbase + mi * 16 + (lane >> 2);
            long r1 = r0 + 8;
            __half2 h0 = *reinterpret_cast<const __half2*>(gscratch + r0 * 512 + c0);
            __half2 h1 = *reinterpret_cast<const __half2*>(gscratch + r1 * 512 + c0);
            float g00 = __half2float(h0.x), g01 = __half2float(h0.y);
            float g10 = __half2float(h1.x), g11 = __half2float(h1.y);
            float2 x0 = *reinterpret_cast<const float2*>(x + r0 * 512 + c0);
            float2 x1 = *reinterpret_cast<const float2*>(x + r1 * 512 + c0);
            float2 o0, o1;
            o0.x = g00 * (acco[mi][ni][0] + b0) + (1.f - g00) * x0.x;
            o0.y = g01 * (acco[mi][ni][1] + b1) + (1.f - g01) * x0.y;
            o1.x = g10 * (acco[mi][ni][2] + b0) + (1.f - g10) * x1.x;
            o1.y = g11 * (acco[mi][ni][3] + b1) + (1.f - g11) * x1.y;
            *reinterpret_cast<float2*>(out + r0 * 512 + c0) = o0;
            *reinterpret_cast<float2*>(out + r1 * 512 + c0) = o1;
        }
    }
}

// ------- k_lnmix (512 thr): x_t = gelu(LN(h)); weighted = adj @ x_t  -------
#define MIX_ASTR 56
#define MIX_BSTR 520
#define MIX_SMEM ((48 * MIX_ASTR + 48 * MIX_BSTR) * 2)

__global__ void __launch_bounds__(512) k_lnmix(const bf16* __restrict__ h,
                                               const float* __restrict__ lg,
                                               const float* __restrict__ lb) {
    extern __shared__ bf16 msm[];
    bf16* sadj = msm;                       // 48 x MIX_ASTR
    bf16* sxt = msm + 48 * MIX_ASTR;        // 48 x MIX_BSTR  (h, then x_t in place)
    const int b = blockIdx.x;
    const int tid = threadIdx.x;
    const int lane = tid & 31;
    const int wid = tid >> 5;               // 0..15

    // adj fp32 -> bf16 smem
    for (int i = tid; i < SEQL * SEQL; i += 512) {
        int r = i / SEQL, c = i - r * SEQL;
        sadj[r * MIX_ASTR + c] = __float2bfloat16(g_adj[i]);
    }
    // h batch tile: 48 rows x 512 cols
    const uint4* src = reinterpret_cast<const uint4*>(h + (size_t)b * SEQL * 512);
    for (int v = tid; v < SEQL * 64; v += 512) {
        int j = v >> 6, gq = v & 63;
        *reinterpret_cast<uint4*>(&sxt[j * MIX_BSTR + gq * 8]) = src[v];
    }
    __syncthreads();

    // LN + gelu in-smem: warp wid handles rows wid, wid+16, wid+32  (3 rows/warp)
    bf16* xt_out = g_xt + (size_t)b * SEQL * 512;
    for (int rr = wid; rr < SEQL; rr += 16) {
        bf16* rowp = sxt + rr * MIX_BSTR;
        float v[16];
        float s = 0.f, s2 = 0.f;
        #pragma unroll
        for (int i = 0; i < 4; i++) {
            int c = (i * 32 + lane) * 4;
            uint2 u = *reinterpret_cast<const uint2*>(rowp + c);
            __nv_bfloat162 p0 = *reinterpret_cast<__nv_bfloat162*>(&u.x);
            __nv_bfloat162 p1 = *reinterpret_cast<__nv_bfloat162*>(&u.y);
            v[i * 4 + 0] = __bfloat162float(p0.x);
            v[i * 4 + 1] = __bfloat162float(p0.y);
            v[i * 4 + 2] = __bfloat162float(p1.x);
            v[i * 4 + 3] = __bfloat162float(p1.y);
            s += v[i * 4 + 0] + v[i * 4 + 1] + v[i * 4 + 2] + v[i * 4 + 3];
            s2 += v[i * 4 + 0] * v[i * 4 + 0] + v[i * 4 + 1] * v[i * 4 + 1] +
                  v[i * 4 + 2] * v[i * 4 + 2] + v[i * 4 + 3] * v[i * 4 + 3];
        }
        #pragma unroll
        for (int o = 16; o > 0; o >>= 1) {
            s += __shfl_xor_sync(0xffffffffu, s, o);
            s2 += __shfl_xor_sync(0xffffffffu, s2, o);
        }
        float mu = s * (1.f / 512.f);
        float var = s2 * (1.f / 512.f) - mu * mu;
        float rstd = rsqrtf(var + 1e-5f);
        #pragma unroll
        for (int i = 0; i < 4; i++) {
            int c = (i * 32 + lane) * 4;
            float4 gv = *reinterpret_cast<const float4*>(lg + c);
            float4 bv = *reinterpret_cast<const float4*>(lb + c);
            float y0 = geluf((v[i * 4 + 0] - mu) * rstd * gv.x + bv.x);
            float y1 = geluf((v[i * 4 + 1] - mu) * rstd * gv.y + bv.y);
            float y2 = geluf((v[i * 4 + 2] - mu) * rstd * gv.z + bv.z);
            float y3 = geluf((v[i * 4 + 3] - mu) * rstd * gv.w + bv.w);
            __nv_bfloat162 p0 = __floats2bfloat162_rn(y0, y1);
            __nv_bfloat162 p1 = __floats2bfloat162_rn(y2, y3);
            uint2 u;
            u.x = *reinterpret_cast<unsigned*>(&p0);
            u.y = *reinterpret_cast<unsigned*>(&p1);
            *reinterpret_cast<uint2*>(rowp + c) = u;
            *reinterpret_cast<uint2*>(xt_out + (long)rr * 512 + c) = u;
        }
    }
    __syncthreads();

    // MMA: weighted = sadj @ sxt; warp covers 48 rows x 32 cols (nbase = wid*32)
    unsigned aBase = (unsigned)__cvta_generic_to_shared(sadj);
    unsigned bBase = (unsigned)__cvta_generic_to_shared(sxt);
    float acc[3][4][4] = {};
    const int nbase = wid * 32;

    #pragma unroll
    for (int kt = 0; kt < 3; kt++) {
        unsigned a[3][4];
        #pragma unroll
        for (int mt = 0; mt < 3; mt++) {
            int r = mt * 16 + (lane & 15);
            int c = kt * 16 + ((lane >> 4) << 3);
            unsigned addr = aBase + (unsigned)((r * MIX_ASTR + c) * 2);
            asm volatile("ldmatrix.sync.aligned.m8n8.x4.shared.b16 {%0,%1,%2,%3}, [%4];\n"
                         : "=r"(a[mt][0]), "=r"(a[mt][1]), "=r"(a[mt][2]), "=r"(a[mt][3])
                         : "r"(addr));
        }
        #pragma unroll
        for (int nt = 0; nt < 2; nt++) {
            unsigned bf[4];
            int r = kt * 16 + (lane & 15);
            int c = nbase + nt * 16 + ((lane >> 4) << 3);
            unsigned addr = bBase + (unsigned)((r * MIX_BSTR + c) * 2);
            asm volatile("ldmatrix.sync.aligned.m8n8.x4.trans.shared.b16 {%0,%1,%2,%3}, [%4];\n"
                         : "=r"(bf[0]), "=r"(bf[1]), "=r"(bf[2]), "=r"(bf[3])
                         : "r"(addr));
            #pragma unroll
            for (int mt = 0; mt < 3; mt++)
                #pragma unroll
                for (int nj = 0; nj < 2; nj++) {
                    int ni = nt * 2 + nj;
                    asm volatile(
                        "mma.sync.aligned.m16n8k16.row.col.f32.bf16.bf16.f32 "
                        "{%0,%1,%2,%3}, {%4,%5,%6,%7}, {%8,%9}, {%0,%1,%2,%3};\n"
                        : "+f"(acc[mt][ni][0]), "+f"(acc[mt][ni][1]),
                          "+f"(acc[mt][ni][2]), "+f"(acc[mt][ni][3])
                        : "r"(a[mt][0]), "r"(a[mt][1]), "r"(a[mt][2]), "r"(a[mt][3]),
                          "r"(bf[nj * 2]), "r"(bf[nj * 2 + 1]));
                }
        }
    }

    bf16* o = g_wt + (size_t)b * SEQL * 512;
    #pragma unroll
    for (int mt = 0; mt < 3; mt++) {
        #pragma unroll
        for (int ni = 0; ni < 4; ni++) {
            int c0 = nbase + ni * 8 + (lane & 3) * 2;
            int r0 = mt * 16 + (lane >> 2);
            int r1 = r0 + 8;
            __nv_bfloat162 p0 = __floats2bfloat162_rn(acc[mt][ni][0], acc[mt][ni][1]);
            __nv_bfloat162 p1 = __floats2bfloat162_rn(acc[mt][ni][2], acc[mt][ni][3]);
            *reinterpret_cast<__nv_bfloat162*>(o + (long)r0 * 512 + c0) = p0;
            *reinterpret_cast<__nv_bfloat162*>(o + (long)r1 * 512 + c0) = p1;
        }
    }
}

// ---------------- launch ----------------
extern "C" void kernel_launch(void* const* d_in, const int* in_sizes, int n_in,
                              void* d_out, int out_size) {
    const float* x = (const float*)d_in[0];
    const float* lw = (const float*)d_in[1];
    const float* Wnt = (const float*)d_in[2];
    const float* bnt = (const float*)d_in[3];
    const float* lng = (const float*)d_in[4];
    const float* lnb = (const float*)d_in[5];
    const float* We1 = (const float*)d_in[6];
    const float* be1 = (const float*)d_in[7];
    const float* We2 = (const float*)d_in[8];
    const float* be2 = (const float*)d_in[9];
    const float* Wo = (const float*)d_in[10];
    const float* bo = (const float*)d_in[11];
    const float* Wg = (const float*)d_in[12];
    const float* bg = (const float*)d_in[13];
    float* out = (float*)d_out;

    void *p_wnt, *p_we1, *p_we2, *p_wo, *p_wg, *p_xbf, *p_hbf, *p_xt, *p_wt, *p_h1, *p_msg;
    cudaGetSymbolAddress(&p_wnt, g_wnt);
    cudaGetSymbolAddress(&p_we1, g_we1);
    cudaGetSymbolAddress(&p_we2, g_we2);
    cudaGetSymbolAddress(&p_wo, g_wo);
    cudaGetSymbolAddress(&p_wg, g_wg);
    cudaGetSymbolAddress(&p_xbf, g_xbf);
    cudaGetSymbolAddress(&p_hbf, g_hbf);
    cudaGetSymbolAddress(&p_xt, g_xt);
    cudaGetSymbolAddress(&p_wt, g_wt);
    cudaGetSymbolAddress(&p_h1, g_h1);
    cudaGetSymbolAddress(&p_msg, g_msg);

    static bool attr_done = false;
    if (!attr_done) {
        cudaFuncSetAttribute(gemm_k<512, false, EPI_HBF>,
                             cudaFuncAttributeMaxDynamicSharedMemorySize, SMEM_BYTES);
        cudaFuncSetAttribute(gemm_k<1024, true, EPI_GELU>,
                             cudaFuncAttributeMaxDynamicSharedMemorySize, SMEM_BYTES);
        cudaFuncSetAttribute(gemm_k<512, false, EPI_MSG>,
                             cudaFuncAttributeMaxDynamicSharedMemorySize, SMEM_BYTES);
        cudaFuncSetAttribute(gemm_fused,
                             cudaFuncAttributeMaxDynamicSharedMemorySize, SMEM_BYTES);
        cudaFuncSetAttribute(k_lnmix,
                             cudaFuncAttributeMaxDynamicSharedMemorySize, MIX_SMEM);
        attr_done = true;
    }

    dim3 gg(4, MROWS / 128);  // 128x128 tiles, bn fast -> A-tile L2 reuse

    // 1: convert x + weights to bf16 (single launch)
    k_prep<<<2304, 256>>>(x, Wnt, We1, We2, Wo, Wg);
    // 2: adjacency
    k_adj<<<1, 64>>>(lw);
    // 3: h = x@Wnt + bnt (bf16 out)
    gemm_k<512, false, EPI_HBF><<<gg, 256, SMEM_BYTES>>>(
        (const bf16*)p_xbf, nullptr, (const bf16*)p_wnt, bnt, p_hbf);
    // 4 <- ncu capture: fused x_t = gelu(LN(h)); weighted = adj @ x_t  (512 thr)
    k_lnmix<<<4096, 512, MIX_SMEM>>>((const bf16*)p_hbf, lng, lnb);
    // 5: h1 = gelu([x_t|wt]@We1 + be1)
    gemm_k<1024, true, EPI_GELU><<<gg, 256, SMEM_BYTES>>>(
        (const bf16*)p_xt, (const bf16*)p_wt, (const bf16*)p_we1, be1, p_h1);
    // 6: messages = blend(h1@We2 + be2, x_t)
    gemm_k<512, false, EPI_MSG><<<gg, 256, SMEM_BYTES>>>(
        (const bf16*)p_h1, nullptr, (const bf16*)p_we2, be2, p_msg);
    // 7: fused gate + Wo + blend -> out (h buffer reused as fp16 gate scratch)
    gemm_fused<<<gg, 256, SMEM_BYTES>>>(
        (const bf16*)p_xbf, (const bf16*)p_msg, (const bf16*)p_wg, bg,
        (const bf16*)p_wo, bo, x, out, (__half*)p_hbf);
}

// round 16
// speedup vs baseline: 1.0272x; 1.0125x over previous
#include <cuda_runtime.h>
#include <cuda_bf16.h>
#include <cuda_fp16.h>
#include <math.h>
#include <stdint.h>

#define MROWS 196608
#define SEQL 48
typedef __nv_bfloat16 bf16;

// ---------------- device scratch ----------------
__device__ __align__(128) bf16 g_wnt[512 * 512];
__device__ __align__(128) bf16 g_we1[1024 * 512];
__device__ __align__(128) bf16 g_we2[512 * 512];
__device__ __align__(128) bf16 g_wo[512 * 512];
__device__ __align__(128) bf16 g_wg[1024 * 512];
__device__ __align__(128) bf16 g_xbf[(size_t)MROWS * 512];
__device__ __align__(128) bf16 g_hbf[(size_t)MROWS * 512];   // h (bf16), later fp16 gate scratch
__device__ __align__(128) bf16 g_xt[(size_t)MROWS * 512];
__device__ __align__(128) bf16 g_wt[(size_t)MROWS * 512];
__device__ __align__(128) bf16 g_h1[(size_t)MROWS * 512];
__device__ __align__(128) bf16 g_msg[(size_t)MROWS * 512];
__device__ float g_adj[SEQL * SEQL];
__device__ int g_hasnb[SEQL];

__device__ __forceinline__ float geluf(float x) {
    return 0.5f * x * (1.0f + erff(x * 0.7071067811865476f));
}
__device__ __forceinline__ float sigf(float x) { return 1.f / (1.f + expf(-x)); }

__device__ __forceinline__ void cp16(unsigned dst, const void* src) {
    asm volatile("cp.async.cg.shared.global [%0], [%1], 16;\n" :: "r"(dst), "l"(src));
}

// ---------------- prep: x + all weights -> bf16 (single launch) ----------------
__global__ void k_prep(const float* __restrict__ x, const float* __restrict__ Wnt,
                       const float* __restrict__ We1, const float* __restrict__ We2,
                       const float* __restrict__ Wo, const float* __restrict__ Wg) {
    const long Q0 = (long)MROWS * 512 / 4;
    const long Q1 = 65536, Q2 = 131072, Q3 = 65536, Q4 = 65536, Q5 = 131072;
    const long QT = Q0 + Q1 + Q2 + Q3 + Q4 + Q5;
    for (long q = (long)blockIdx.x * blockDim.x + threadIdx.x; q < QT;
         q += (long)gridDim.x * blockDim.x) {
        const float* s; bf16* d; long o;
        if (q < Q0) { s = x; d = g_xbf; o = q; }
        else if (q < Q0 + Q1) { s = Wnt; d = g_wnt; o = q - Q0; }
        else if (q < Q0 + Q1 + Q2) { s = We1; d = g_we1; o = q - Q0 - Q1; }
        else if (q < Q0 + Q1 + Q2 + Q3) { s = We2; d = g_we2; o = q - Q0 - Q1 - Q2; }
        else if (q < Q0 + Q1 + Q2 + Q3 + Q4) { s = Wo; d = g_wo; o = q - Q0 - Q1 - Q2 - Q3; }
        else { s = Wg; d = g_wg; o = q - Q0 - Q1 - Q2 - Q3 - Q4; }
        float4 f = reinterpret_cast<const float4*>(s)[o];
        __nv_bfloat162 p0 = __floats2bfloat162_rn(f.x, f.y);
        __nv_bfloat162 p1 = __floats2bfloat162_rn(f.z, f.w);
        uint2 u;
        u.x = *reinterpret_cast<unsigned*>(&p0);
        u.y = *reinterpret_cast<unsigned*>(&p1);
        reinterpret_cast<uint2*>(d)[o] = u;
    }
}

__global__ void k_adj(const float* __restrict__ lw) {
    int i = threadIdx.x;
    if (i >= SEQL) return;
    float v[SEQL];
    float mx = -1e30f;
    #pragma unroll
    for (int j = 0; j < SEQL; j++) { v[j] = lw[i * SEQL + j]; mx = fmaxf(mx, v[j]); }
    float s = 0.f;
    #pragma unroll
    for (int j = 0; j < SEQL; j++) { v[j] = expf(v[j] - mx); s += v[j]; }
    float inv = 1.f / s;
    int any = 0;
    #pragma unroll
    for (int j = 0; j < SEQL; j++) {
        float a = v[j] * inv;
        int nb = (a > 0.01f);
        g_adj[i * SEQL + j] = nb ? a : 0.f;
        any |= nb;
    }
    g_hasnb[i] = any;
}

// ---------------- GEMM core (128x128, 256 thr, 3-stage, 2 CTA/SM) ----------
enum { EPI_HBF = 0, EPI_GELU = 1, EPI_MSG = 2 };

#define STAGES 3
#define ASTR 72
#define BSTR 136
#define A_ELEMS (128 * ASTR)
#define B_ELEMS (64 * BSTR)
#define SMEM_BYTES (STAGES * (A_ELEMS + B_ELEMS) * 2)

#define GEMM_PRELUDE                                                     \
    extern __shared__ bf16 smem[];                                       \
    const int tid = threadIdx.x;                                         \
    const int lane = tid & 31;                                           \
    const int wid = tid >> 5;                                            \
    const int wm = wid >> 1;                                             \
    const int wn = wid & 1;                                              \
    const int bn = blockIdx.x;                                           \
    const int bm = blockIdx.y;                                           \
    unsigned sbase = (unsigned)__cvta_generic_to_shared(smem);           \
    unsigned aB = sbase;                                                 \
    unsigned bB = sbase + STAGES * A_ELEMS * 2;

#define DEF_COMPUTE                                                                      \
    auto compute = [&](int st, float (&acc)[2][8][4]) {                                  \
        unsigned ab = aB + st * A_ELEMS * 2;                                             \
        unsigned bb = bB + st * B_ELEMS * 2;                                             \
        _Pragma("unroll")                                                                \
        for (int kk = 0; kk < 64; kk += 16) {                                            \
            unsigned a[2][4];                                                            \
            _Pragma("unroll")                                                            \
            for (int mi = 0; mi < 2; mi++) {                                             \
                int r = wm * 32 + mi * 16 + (lane & 15);                                 \
                int c = kk + ((lane >> 4) << 3);                                         \
                unsigned addr = ab + (unsigned)((r * ASTR + c) * 2);                     \
                asm volatile(                                                            \
                    "ldmatrix.sync.aligned.m8n8.x4.shared.b16 {%0,%1,%2,%3}, [%4];\n"    \
                    : "=r"(a[mi][0]), "=r"(a[mi][1]), "=r"(a[mi][2]), "=r"(a[mi][3])     \
                    : "r"(addr));                                                        \
            }                                                                            \
            unsigned b[4][4];                                                            \
            _Pragma("unroll")                                                            \
            for (int bi = 0; bi < 4; bi++) {                                             \
                int r = kk + (lane & 15);                                                \
                int c = wn * 64 + bi * 16 + ((lane >> 4) << 3);                          \
                unsigned addr = bb + (unsigned)((r * BSTR + c) * 2);                     \
                asm volatile(                                                            \
                    "ldmatrix.sync.aligned.m8n8.x4.trans.shared.b16 {%0,%1,%2,%3}, "     \
                    "[%4];\n"                                                            \
                    : "=r"(b[bi][0]), "=r"(b[bi][1]), "=r"(b[bi][2]), "=r"(b[bi][3])     \
                    : "r"(addr));                                                        \
            }                                                                            \
            _Pragma("unroll")                                                            \
            for (int mi = 0; mi < 2; mi++)                                               \
                _Pragma("unroll")                                                        \
                for (int ni = 0; ni < 8; ni++) {                                         \
                    unsigned b0 = b[ni >> 1][(ni & 1) * 2];                              \
                    unsigned b1 = b[ni >> 1][(ni & 1) * 2 + 1];                          \
                    asm volatile(                                                        \
                        "mma.sync.aligned.m16n8k16.row.col.f32.bf16.bf16.f32 "           \
                        "{%0,%1,%2,%3}, {%4,%5,%6,%7}, {%8,%9}, {%0,%1,%2,%3};\n"        \
                        : "+f"(acc[mi][ni][0]), "+f"(acc[mi][ni][1]),                    \
                          "+f"(acc[mi][ni][2]), "+f"(acc[mi][ni][3])                     \
                        : "r"(a[mi][0]), "r"(a[mi][1]), "r"(a[mi][2]), "r"(a[mi][3]),    \
                          "r"(b0), "r"(b1));                                             \
                }                                                                        \
        }                                                                                \
    };

#define DEF_LOADER                                                                       \
    auto load_stage = [&](int kt, int st, const bf16* A0, const bf16* A1,                \
                          const bf16* W, bool concat) {                                  \
        unsigned ab = aB + st * A_ELEMS * 2;                                             \
        unsigned bb = bB + st * B_ELEMS * 2;                                             \
        _Pragma("unroll")                                                                \
        for (int i = 0; i < 4; i++) {                                                    \
            int v = tid + (i << 8);                                                      \
            int row = v >> 3;                                                            \
            int kc = (v & 7) << 3;                                                       \
            long grow = (long)bm * 128 + row;                                            \
            int gk = kt * 64 + kc;                                                       \
            const bf16* src = (concat && gk >= 512) ? A1 + grow * 512 + (gk - 512)       \
                                                    : A0 + grow * 512 + gk;              \
            cp16(ab + (unsigned)((row * ASTR + kc) * 2), src);                           \
        }                                                                                \
        _Pragma("unroll")                                                                \
        for (int i = 0; i < 4; i++) {                                                    \
            int v = tid + (i << 8);                                                      \
            int row = v >> 4;                                                            \
            int nc = (v & 15) << 3;                                                      \
            cp16(bb + (unsigned)((row * BSTR + nc) * 2),                                 \
                 W + (long)(kt * 64 + row) * 512 + bn * 128 + nc);                       \
        }                                                                                \
        asm volatile("cp.async.commit_group;\n");                                       \
    };

#define RUN_PIPELINE(NK, A0, A1, W, CC, ACC)                                             \
    load_stage(0, 0, A0, A1, W, CC);                                                     \
    load_stage(1, 1, A0, A1, W, CC);                                                     \
    for (int kt = 0; kt < (NK); kt++) {                                                  \
        if (kt + 1 < (NK)) asm volatile("cp.async.wait_group 1;\n");                     \
        else asm volatile("cp.async.wait_group 0;\n");                                   \
        __syncthreads();                                                                 \
        if (kt + 2 < (NK)) load_stage(kt + 2, (kt + 2) % STAGES, A0, A1, W, CC);         \
        compute(kt % STAGES, ACC);                                                       \
    }

// ---------------- standalone GEMM ----------------
template <int KTOT, bool CONCAT, int EPI>
__global__ void __launch_bounds__(256, 2) gemm_k(
    const bf16* __restrict__ A0, const bf16* __restrict__ A1,
    const bf16* __restrict__ W, const float* __restrict__ bias,
    void* __restrict__ outp)
{
    GEMM_PRELUDE
    DEF_COMPUTE
    DEF_LOADER
    float acc[2][8][4] = {};
    const int nk = KTOT / 64;
    RUN_PIPELINE(nk, A0, A1, W, CONCAT, acc)

    long rbase = (long)bm * 128 + wm * 32;
    int cbase = bn * 128 + wn * 64;
    #pragma unroll
    for (int mi = 0; mi < 2; mi++) {
        #pragma unroll
        for (int ni = 0; ni < 8; ni++) {
            int c0 = cbase + ni * 8 + (lane & 3) * 2;
            float bv0 = bias[c0], bv1 = bias[c0 + 1];
            long r0 = rbase + mi * 16 + (lane >> 2);
            long r1 = r0 + 8;
            float v00 = acc[mi][ni][0] + bv0;
            float v01 = acc[mi][ni][1] + bv1;
            float v10 = acc[mi][ni][2] + bv0;
            float v11 = acc[mi][ni][3] + bv1;
            bf16* o = (bf16*)outp;
            if (EPI == EPI_GELU) {
                v00 = geluf(v00); v01 = geluf(v01);
                v10 = geluf(v10); v11 = geluf(v11);
            } else if (EPI == EPI_MSG) {
                int s0 = (int)(r0 % SEQL), s1 = (int)(r1 % SEQL);
                if (!g_hasnb[s0]) {
                    v00 = __bfloat162float(g_xt[r0 * 512 + c0]);
                    v01 = __bfloat162float(g_xt[r0 * 512 + c0 + 1]);
                }
                if (!g_hasnb[s1]) {
                    v10 = __bfloat162float(g_xt[r1 * 512 + c0]);
                    v11 = __bfloat162float(g_xt[r1 * 512 + c0 + 1]);
                }
            }
            __nv_bfloat162 p0 = __floats2bfloat162_rn(v00, v01);
            __nv_bfloat162 p1 = __floats2bfloat162_rn(v10, v11);
            *reinterpret_cast<__nv_bfloat162*>(o + r0 * 512 + c0) = p0;
            *reinterpret_cast<__nv_bfloat162*>(o + r1 * 512 + c0) = p1;
        }
    }
}

// ---- fused gate + Wo + blend; gate spilled to fp16 gmem scratch (L2-resident) ----
__global__ void __launch_bounds__(256, 2) gemm_fused(
    const bf16* __restrict__ xbf, const bf16* __restrict__ msg,
    const bf16* __restrict__ Wg, const float* __restrict__ bg,
    const bf16* __restrict__ Wo, const float* __restrict__ bo,
    const float* __restrict__ x, float* __restrict__ out,
    __half* __restrict__ gscratch)
{
    GEMM_PRELUDE
    DEF_COMPUTE
    DEF_LOADER

    long rbase = (long)bm * 128 + wm * 32;
    int cbase = bn * 128 + wn * 64;

    // phase 1: gate logits over [xbf | msg] @ Wg, K=1024
    {
        float accg[2][8][4] = {};
        RUN_PIPELINE(16, xbf, msg, Wg, true, accg)

        #pragma unroll
        for (int mi = 0; mi < 2; mi++)
            #pragma unroll
            for (int ni = 0; ni < 8; ni++) {
                int c0 = cbase + ni * 8 + (lane & 3) * 2;
                float b0 = bg[c0], b1 = bg[c0 + 1];
                long r0 = rbase + mi * 16 + (lane >> 2);
                long r1 = r0 + 8;
                __half2 h0 = __floats2half2_rn(sigf(accg[mi][ni][0] + b0),
                                               sigf(accg[mi][ni][1] + b1));
                __half2 h1 = __floats2half2_rn(sigf(accg[mi][ni][2] + b0),
                                               sigf(accg[mi][ni][3] + b1));
                *reinterpret_cast<__half2*>(gscratch + r0 * 512 + c0) = h0;
                *reinterpret_cast<__half2*>(gscratch + r1 * 512 + c0) = h1;
            }
    }

    __syncthreads();

    // phase 2: mo = msg @ Wo, K=512
    float acco[2][8][4] = {};
    RUN_PIPELINE(8, msg, msg, Wo, false, acco)

    #pragma unroll
    for (int mi = 0; mi < 2; mi++) {
        #pragma unroll
        for (int ni = 0; ni < 8; ni++) {
            int c0 = cbase + ni * 8 + (lane & 3) * 2;
            float b0 = bo[c0], b1 = bo[c0 + 1];
            long r0 = rbase + mi * 16 + (lane >> 2);
            long r1 = r0 + 8;
            __half2 h0 = *reinterpret_cast<const __half2*>(gscratch + r0 * 512 + c0);
            __half2 h1 = *reinterpret_cast<const __half2*>(gscratch + r1 * 512 + c0);
            float g00 = __half2float(h0.x), g01 = __half2float(h0.y);
            float g10 = __half2float(h1.x), g11 = __half2float(h1.y);
            float2 x0 = *reinterpret_cast<const float2*>(x + r0 * 512 + c0);
            float2 x1 = *reinterpret_cast<const float2*>(x + r1 * 512 + c0);
            float2 o0, o1;
            o0.x = g00 * (acco[mi][ni][0] + b0) + (1.f - g00) * x0.x;
            o0.y = g01 * (acco[mi][ni][1] + b1) + (1.f - g01) * x0.y;
            o1.x = g10 * (acco[mi][ni][2] + b0) + (1.f - g10) * x1.x;
            o1.y = g11 * (acco[mi][ni][3] + b1) + (1.f - g11) * x1.y;
            *reinterpret_cast<float2*>(out + r0 * 512 + c0) = o0;
            *reinterpret_cast<float2*>(out + r1 * 512 + c0) = o1;
        }
    }
}

// ------- k_lnmix (512 thr): LN reads h from gmem; x_t -> smem+gmem; mix MMA -------
#define MIX_ASTR 56
#define MIX_BSTR 520
#define MIX_SMEM ((48 * MIX_ASTR + 48 * MIX_BSTR) * 2)

__global__ void __launch_bounds__(512) k_lnmix(const bf16* __restrict__ h,
                                               const float* __restrict__ lg,
                                               const float* __restrict__ lb) {
    extern __shared__ bf16 msm[];
    bf16* sadj = msm;                       // 48 x MIX_ASTR
    bf16* sxt = msm + 48 * MIX_ASTR;        // 48 x MIX_BSTR  (x_t only)
    const int b = blockIdx.x;
    const int tid = threadIdx.x;
    const int lane = tid & 31;
    const int wid = tid >> 5;               // 0..15

    // adj fp32 -> bf16 smem
    for (int i = tid; i < SEQL * SEQL; i += 512) {
        int r = i / SEQL, c = i - r * SEQL;
        sadj[r * MIX_ASTR + c] = __float2bfloat16(g_adj[i]);
    }

    // LN + gelu: warp wid handles rows wid, wid+16, wid+32; h read straight from gmem
    bf16* xt_out = g_xt + (size_t)b * SEQL * 512;
    const bf16* hbase = h + (size_t)b * SEQL * 512;
    for (int rr = wid; rr < SEQL; rr += 16) {
        const bf16* hrow = hbase + (long)rr * 512;
        bf16* rowp = sxt + rr * MIX_BSTR;
        float v[16];
        float s = 0.f, s2 = 0.f;
        #pragma unroll
        for (int i = 0; i < 4; i++) {
            int c = (i * 32 + lane) * 4;
            uint2 u = *reinterpret_cast<const uint2*>(hrow + c);
            __nv_bfloat162 p0 = *reinterpret_cast<__nv_bfloat162*>(&u.x);
            __nv_bfloat162 p1 = *reinterpret_cast<__nv_bfloat162*>(&u.y);
            v[i * 4 + 0] = __bfloat162float(p0.x);
            v[i * 4 + 1] = __bfloat162float(p0.y);
            v[i * 4 + 2] = __bfloat162float(p1.x);
            v[i * 4 + 3] = __bfloat162float(p1.y);
            s += v[i * 4 + 0] + v[i * 4 + 1] + v[i * 4 + 2] + v[i * 4 + 3];
            s2 += v[i * 4 + 0] * v[i * 4 + 0] + v[i * 4 + 1] * v[i * 4 + 1] +
                  v[i * 4 + 2] * v[i * 4 + 2] + v[i * 4 + 3] * v[i * 4 + 3];
        }
        #pragma unroll
        for (int o = 16; o > 0; o >>= 1) {
            s += __shfl_xor_sync(0xffffffffu, s, o);
            s2 += __shfl_xor_sync(0xffffffffu, s2, o);
        }
        float mu = s * (1.f / 512.f);
        float var = s2 * (1.f / 512.f) - mu * mu;
        float rstd = rsqrtf(var + 1e-5f);
        #pragma unroll
        for (int i = 0; i < 4; i++) {
            int c = (i * 32 + lane) * 4;
            float4 gv = *reinterpret_cast<const float4*>(lg + c);
            float4 bv = *reinterpret_cast<const float4*>(lb + c);
            float y0 = geluf((v[i * 4 + 0] - mu) * rstd * gv.x + bv.x);
            float y1 = geluf((v[i * 4 + 1] - mu) * rstd * gv.y + bv.y);
            float y2 = geluf((v[i * 4 + 2] - mu) * rstd * gv.z + bv.z);
            float y3 = geluf((v[i * 4 + 3] - mu) * rstd * gv.w + bv.w);
            __nv_bfloat162 p0 = __floats2bfloat162_rn(y0, y1);
            __nv_bfloat162 p1 = __floats2bfloat162_rn(y2, y3);
            uint2 u;
            u.x = *reinterpret_cast<unsigned*>(&p0);
            u.y = *reinterpret_cast<unsigned*>(&p1);
            *reinterpret_cast<uint2*>(rowp + c) = u;
            *reinterpret_cast<uint2*>(xt_out + (long)rr * 512 + c) = u;
        }
    }
    __syncthreads();

    // MMA: weighted = sadj @ sxt; warp covers 48 rows x 32 cols (nbase = wid*32)
    unsigned aBase = (unsigned)__cvta_generic_to_shared(sadj);
    unsigned bBase = (unsigned)__cvta_generic_to_shared(sxt);
    float acc[3][4][4] = {};
    const int nbase = wid * 32;

    #pragma unroll
    for (int kt = 0; kt < 3; kt++) {
        unsigned a[3][4];
        #pragma unroll
        for (int mt = 0; mt < 3; mt++) {
            int r = mt * 16 + (lane & 15);
            int c = kt * 16 + ((lane >> 4) << 3);
            unsigned addr = aBase + (unsigned)((r * MIX_ASTR + c) * 2);
            asm volatile("ldmatrix.sync.aligned.m8n8.x4.shared.b16 {%0,%1,%2,%3}, [%4];\n"
                         : "=r"(a[mt][0]), "=r"(a[mt][1]), "=r"(a[mt][2]), "=r"(a[mt][3])
                         : "r"(addr));
        }
        #pragma unroll
        for (int nt = 0; nt < 2; nt++) {
            unsigned bf[4];
            int r = kt * 16 + (lane & 15);
            int c = nbase + nt * 16 + ((lane >> 4) << 3);
            unsigned addr = bBase + (unsigned)((r * MIX_BSTR + c) * 2);
            asm volatile("ldmatrix.sync.aligned.m8n8.x4.trans.shared.b16 {%0,%1,%2,%3}, [%4];\n"
                         : "=r"(bf[0]), "=r"(bf[1]), "=r"(bf[2]), "=r"(bf[3])
                         : "r"(addr));
            #pragma unroll
            for (int mt = 0; mt < 3; mt++)
                #pragma unroll
                for (int nj = 0; nj < 2; nj++) {
                    int ni = nt * 2 + nj;
                    asm volatile(
                        "mma.sync.aligned.m16n8k16.row.col.f32.bf16.bf16.f32 "
                        "{%0,%1,%2,%3}, {%4,%5,%6,%7}, {%8,%9}, {%0,%1,%2,%3};\n"
                        : "+f"(acc[mt][ni][0]), "+f"(acc[mt][ni][1]),
                          "+f"(acc[mt][ni][2]), "+f"(acc[mt][ni][3])
                        : "r"(a[mt][0]), "r"(a[mt][1]), "r"(a[mt][2]), "r"(a[mt][3]),
                          "r"(bf[nj * 2]), "r"(bf[nj * 2 + 1]));
                }
        }
    }

    bf16* o = g_wt + (size_t)b * SEQL * 512;
    #pragma unroll
    for (int mt = 0; mt < 3; mt++) {
        #pragma unroll
        for (int ni = 0; ni < 4; ni++) {
            int c0 = nbase + ni * 8 + (lane & 3) * 2;
            int r0 = mt * 16 + (lane >> 2);
            int r1 = r0 + 8;
            __nv_bfloat162 p0 = __floats2bfloat162_rn(acc[mt][ni][0], acc[mt][ni][1]);
            __nv_bfloat162 p1 = __floats2bfloat162_rn(acc[mt][ni][2], acc[mt][ni][3]);
            *reinterpret_cast<__nv_bfloat162*>(o + (long)r0 * 512 + c0) = p0;
            *reinterpret_cast<__nv_bfloat162*>(o + (long)r1 * 512 + c0) = p1;
        }
    }
}

// ---------------- launch ----------------
extern "C" void kernel_launch(void* const* d_in, const int* in_sizes, int n_in,
                              void* d_out, int out_size) {
    const float* x = (const float*)d_in[0];
    const float* lw = (const float*)d_in[1];
    const float* Wnt = (const float*)d_in[2];
    const float* bnt = (const float*)d_in[3];
    const float* lng = (const float*)d_in[4];
    const float* lnb = (const float*)d_in[5];
    const float* We1 = (const float*)d_in[6];
    const float* be1 = (const float*)d_in[7];
    const float* We2 = (const float*)d_in[8];
    const float* be2 = (const float*)d_in[9];
    const float* Wo = (const float*)d_in[10];
    const float* bo = (const float*)d_in[11];
    const float* Wg = (const float*)d_in[12];
    const float* bg = (const float*)d_in[13];
    float* out = (float*)d_out;

    void *p_wnt, *p_we1, *p_we2, *p_wo, *p_wg, *p_xbf, *p_hbf, *p_xt, *p_wt, *p_h1, *p_msg;
    cudaGetSymbolAddress(&p_wnt, g_wnt);
    cudaGetSymbolAddress(&p_we1, g_we1);
    cudaGetSymbolAddress(&p_we2, g_we2);
    cudaGetSymbolAddress(&p_wo, g_wo);
    cudaGetSymbolAddress(&p_wg, g_wg);
    cudaGetSymbolAddress(&p_xbf, g_xbf);
    cudaGetSymbolAddress(&p_hbf, g_hbf);
    cudaGetSymbolAddress(&p_xt, g_xt);
    cudaGetSymbolAddress(&p_wt, g_wt);
    cudaGetSymbolAddress(&p_h1, g_h1);
    cudaGetSymbolAddress(&p_msg, g_msg);

    static bool attr_done = false;
    if (!attr_done) {
        cudaFuncSetAttribute(gemm_k<512, false, EPI_HBF>,
                             cudaFuncAttributeMaxDynamicSharedMemorySize, SMEM_BYTES);
        cudaFuncSetAttribute(gemm_k<1024, true, EPI_GELU>,
                             cudaFuncAttributeMaxDynamicSharedMemorySize, SMEM_BYTES);
        cudaFuncSetAttribute(gemm_k<512, false, EPI_MSG>,
                             cudaFuncAttributeMaxDynamicSharedMemorySize, SMEM_BYTES);
        cudaFuncSetAttribute(gemm_fused,
                             cudaFuncAttributeMaxDynamicSharedMemorySize, SMEM_BYTES);
        cudaFuncSetAttribute(k_lnmix,
                             cudaFuncAttributeMaxDynamicSharedMemorySize, MIX_SMEM);
        attr_done = true;
    }

    dim3 gg(4, MROWS / 128);  // 128x128 tiles, bn fast -> A-tile L2 reuse

    // 1: convert x + weights to bf16 (single launch)
    k_prep<<<2304, 256>>>(x, Wnt, We1, We2, Wo, Wg);
    // 2: adjacency
    k_adj<<<1, 64>>>(lw);
    // 3: h = x@Wnt + bnt (bf16 out)
    gemm_k<512, false, EPI_HBF><<<gg, 256, SMEM_BYTES>>>(
        (const bf16*)p_xbf, nullptr, (const bf16*)p_wnt, bnt, p_hbf);
    // 4 <- ncu capture: fused x_t = gelu(LN(h)) [gmem-direct]; weighted = adj @ x_t
    k_lnmix<<<4096, 512, MIX_SMEM>>>((const bf16*)p_hbf, lng, lnb);
    // 5: h1 = gelu([x_t|wt]@We1 + be1)
    gemm_k<1024, true, EPI_GELU><<<gg, 256, SMEM_BYTES>>>(
        (const bf16*)p_xt, (const bf16*)p_wt, (const bf16*)p_we1, be1, p_h1);
    // 6: messages = blend(h1@We2 + be2, x_t)
    gemm_k<512, false, EPI_MSG><<<gg, 256, SMEM_BYTES>>>(
        (const bf16*)p_h1, nullptr, (const bf16*)p_we2, be2, p_msg);
    // 7: fused gate + Wo + blend -> out (h buffer reused as fp16 gate scratch)
    gemm_fused<<<gg, 256, SMEM_BYTES>>>(
        (const bf16*)p_xbf, (const bf16*)p_msg, (const bf16*)p_wg, bg,
        (const bf16*)p_wo, bo, x, out, (__half*)p_hbf);
}